// round 14
// baseline (speedup 1.0000x reference)
#include <cuda_runtime.h>
#include <cuda_fp16.h>
#include <math.h>
#include <stdint.h>

#define B_ 4
#define L_ 4096
#define D_ 2048
#define M_ (B_*L_)            // 16384 rows
#define LCHUNK 128
#define NCHUNK (L_/LCHUNK)    // 32

// GEMM tiling: 128x128 tile, K chunk 64 fp16 (=128B row, SW128 swizzle)
#define KC 64
#define NKCH (D_/KC)          // 32
#define SUB 16384             // 128 rows * 128B
#define STAGE (2*SUB)         // A, B = 32KB
#define SMEM_TOTAL (2*STAGE)  // 64KB double buffered -> 2 CTAs/SM

// ---------------- scratch (device globals; no allocation allowed) ----------
__device__ __half g_gate[33554432];  // [M_, D_] sigmoid(f), fp16
__device__ __half g_bin [33554432];  // [M_, D_] silu(i); becomes swish(o) fp16
__device__ __half g_g   [33554432];  // [M_, D_] g projection, fp16
__device__ float g_cA  [B_*NCHUNK*D_];
__device__ float g_cH  [B_*NCHUNK*D_];
__device__ float g_pre [B_*NCHUNK*D_];
__device__ __half g_Xh[33554432];        // X (fp16 rounded)
__device__ __half g_Wh[4][4194304];      // Wi,Wf,Wg,Wo (fp16 rounded)
__device__ __half g_o[33554432];         // rms-gated out (fp16)

__device__ __forceinline__ float fsigmoid(float x) {
    return 1.0f / (1.0f + __expf(-x));
}

// ---------------------------- PTX helpers ----------------------------------
__device__ __forceinline__ uint32_t smem_u32(const void* p) {
    uint32_t a;
    asm("{ .reg .u64 t; cvta.to.shared.u64 t, %1; cvt.u32.u64 %0, t; }"
        : "=r"(a) : "l"(p));
    return a;
}
__device__ __forceinline__ uint32_t swz128(uint32_t off) {
    return off ^ ((off >> 3) & 0x70);
}
__device__ __forceinline__ void cpa16(uint32_t s, const void* g) {
    asm volatile("cp.async.cg.shared.global [%0], [%1], 16;" :: "r"(s), "l"(g));
}
#define CPA_COMMIT()  asm volatile("cp.async.commit_group;" ::: "memory")
#define CPA_WAIT1()   asm volatile("cp.async.wait_group 1;" ::: "memory")
#define CPA_WAIT0()   asm volatile("cp.async.wait_group 0;" ::: "memory")

__device__ __forceinline__ void ldsm4(uint32_t* r, uint32_t addr) {
    asm volatile("ldmatrix.sync.aligned.m8n8.x4.shared.b16 {%0,%1,%2,%3}, [%4];"
        : "=r"(r[0]), "=r"(r[1]), "=r"(r[2]), "=r"(r[3]) : "r"(addr));
}
__device__ __forceinline__ void mma_f16(float* c, const uint32_t* a,
                                        uint32_t b0, uint32_t b1) {
    asm volatile(
        "mma.sync.aligned.m16n8k16.row.col.f32.f16.f16.f32 "
        "{%0,%1,%2,%3}, {%4,%5,%6,%7}, {%8,%9}, {%0,%1,%2,%3};"
        : "+f"(c[0]), "+f"(c[1]), "+f"(c[2]), "+f"(c[3])
        : "r"(a[0]), "r"(a[1]), "r"(a[2]), "r"(a[3]), "r"(b0), "r"(b1));
}

// ---------------------------------------------------------------------------
// fp32 -> fp16 converts (R11 style: separate, fully-utilized grids)
// ---------------------------------------------------------------------------
__global__ __launch_bounds__(256) void convX_kernel(const float* __restrict__ src) {
    int i = blockIdx.x * 256 + threadIdx.x;          // float4 index
    float4 v = reinterpret_cast<const float4*>(src)[i];
    __half h[4] = {__float2half(v.x), __float2half(v.y),
                   __float2half(v.z), __float2half(v.w)};
    reinterpret_cast<uint2*>(g_Xh)[i] = *reinterpret_cast<uint2*>(h);
}

__global__ __launch_bounds__(256) void convW_kernel(
    const float* __restrict__ w0, const float* __restrict__ w1,
    const float* __restrict__ w2, const float* __restrict__ w3) {
    const float* src = (blockIdx.y == 0) ? w0 : (blockIdx.y == 1) ? w1
                     : (blockIdx.y == 2) ? w2 : w3;
    int i = blockIdx.x * 256 + threadIdx.x;          // float4 index
    float4 v = reinterpret_cast<const float4*>(src)[i];
    __half h[4] = {__float2half(v.x), __float2half(v.y),
                   __float2half(v.z), __float2half(v.w)};
    reinterpret_cast<uint2*>(g_Wh[blockIdx.y])[i] = *reinterpret_cast<uint2*>(h);
}

// ---------------------------------------------------------------------------
// fp16 HMMA GEMM: C[m,n] = sum_k A[m,k]*B[n,k], 1 MMA per product.
// Tile 128x128, K chunk 64, 2-stage double buffer (R11 config), 2 CTAs/SM.
// sel=1: A=X, blockIdx.y: 0 -> Wi(silu)->g_bin, 1 -> Wf(sigm)->g_gate
// sel=2: A=X, Wg (raw) -> g_g
// sel=0: A=g_o, Wo (raw) -> Cext (fp32)
// ---------------------------------------------------------------------------
__global__ __launch_bounds__(256, 2) void gemm_f16(int sel, float* Cext) {
    extern __shared__ char smem[];
    const uint32_t sb = smem_u32(smem);
    const int tid  = threadIdx.x;
    const int lane = tid & 31;
    const int wid  = tid >> 5;
    const int wm   = wid & 3;      // 4 warps over M (32 rows each)
    const int wn   = wid >> 2;     // 2 warps over N (64 cols each)
    const int bn = blockIdx.x;
    const int bm = blockIdx.z;

    const __half *Aw, *Bw;
    __half* Ch = nullptr;
    int mode;                           // 0 silu, 1 sigmoid, 2 raw-f16, 3 raw-f32
    if (sel == 1) {
        Aw = g_Xh;
        if (blockIdx.y == 0) { Bw = g_Wh[0]; Ch = g_bin;  mode = 0; }
        else                 { Bw = g_Wh[1]; Ch = g_gate; mode = 1; }
    } else if (sel == 2) { Aw = g_Xh; Bw = g_Wh[2]; Ch = g_g; mode = 2; }
    else                 { Aw = g_o;  Bw = g_Wh[3]; mode = 3; }

    const size_t rowA = (size_t)bm * 128;
    const size_t rowB = (size_t)bn * 128;

    float acc[2][8][4];
    #pragma unroll
    for (int ma = 0; ma < 2; ma++)
        #pragma unroll
        for (int g = 0; g < 8; g++)
            #pragma unroll
            for (int q = 0; q < 4; q++) acc[ma][g][q] = 0.0f;

    // strength-reduced prefetch
    const int prow = tid >> 3;            // 0..31
    const int pch  = tid & 7;             // 16B chunk in 128B row
    const uint32_t so0 = swz128((uint32_t)prow * 128 + pch * 16);
    const __half* pA = Aw + (rowA + prow) * D_ + pch * 8;
    const __half* pB = Bw + (rowB + prow) * D_ + pch * 8;

    auto prefetch = [&](int c) {
        const uint32_t st = sb + (uint32_t)(c & 1) * STAGE;
        #pragma unroll
        for (int r = 0; r < 4; r++) {
            uint32_t so = so0 + r * 4096;
            size_t   go = (size_t)r * 32 * D_;
            cpa16(st + so,       pA + go);
            cpa16(st + SUB + so, pB + go);
        }
        pA += KC; pB += KC;
        CPA_COMMIT();
    };

    prefetch(0);
    prefetch(1);

    // ldsm bases, pre-swizzled (bits 5,6 of base are 0 pre-swizzle, so
    // swz128(base + ks*32) == swz128(base) ^ (ks*32)).
    const int rowL = lane & 15;
    const int colL = lane >> 4;
    uint32_t arbS[2], brbS[4];
    #pragma unroll
    for (int ma = 0; ma < 2; ma++)
        arbS[ma] = swz128((uint32_t)(wm * 32 + ma * 16 + rowL) * 128 + colL * 16);
    #pragma unroll
    for (int g16 = 0; g16 < 4; g16++)
        brbS[g16] = swz128((uint32_t)(wn * 64 + g16 * 16 + rowL) * 128 + colL * 16)
                  + SUB;

    for (int c = 0; c < NKCH; c++) {
        if (c < NKCH - 1) { CPA_WAIT1(); } else { CPA_WAIT0(); }
        __syncthreads();

        const uint32_t st = sb + (uint32_t)(c & 1) * STAGE;
        #pragma unroll
        for (int ks = 0; ks < 4; ks++) {
            const uint32_t kx = (uint32_t)ks * 32;
            uint32_t ah[2][4];
            #pragma unroll
            for (int ma = 0; ma < 2; ma++)
                ldsm4(ah[ma], st + (arbS[ma] ^ kx));
            #pragma unroll
            for (int g16 = 0; g16 < 4; g16++) {
                uint32_t bh[4];
                ldsm4(bh, st + (brbS[g16] ^ kx));
                #pragma unroll
                for (int na = 0; na < 2; na++)
                    #pragma unroll
                    for (int ma = 0; ma < 2; ma++)
                        mma_f16(acc[ma][g16 * 2 + na], ah[ma], bh[na], bh[na + 2]);
            }
        }
        __syncthreads();
        if (c + 2 < NKCH) prefetch(c + 2);
    }

    // epilogue: fused activation; f16 stores for intermediates, f32 for out
    #pragma unroll
    for (int ma = 0; ma < 2; ma++) {
        #pragma unroll
        for (int g = 0; g < 8; g++) {
            int n = (int)rowB + wn * 64 + (g >> 1) * 16 + (g & 1) * 8 + (lane & 3) * 2;
            size_t m0 = rowA + wm * 32 + ma * 16 + (lane >> 2);
            #pragma unroll
            for (int h = 0; h < 2; h++) {           // h=0: rows, h=1: rows+8
                float v0 = acc[ma][g][h * 2 + 0];
                float v1 = acc[ma][g][h * 2 + 1];
                if (mode == 0)      { v0 = v0 * fsigmoid(v0); v1 = v1 * fsigmoid(v1); }
                else if (mode == 1) { v0 = fsigmoid(v0);      v1 = fsigmoid(v1); }
                size_t off = (m0 + h * 8) * D_ + n;
                if (mode == 3) {
                    *reinterpret_cast<float2*>(&Cext[off]) = make_float2(v0, v1);
                } else {
                    *reinterpret_cast<__half2*>(&Ch[off]) =
                        __floats2half2_rn(v0, v1);
                }
            }
        }
    }
}

// ---------------------------------------------------------------------------
// Chunked linear-recurrence scan: h_t = a_t*h_{t-1} + b_t,  b_t = si*(1-a_t)
// fp16 storage, fp32 math; 2 channels (half2) per thread.
// ---------------------------------------------------------------------------
__global__ void scan_pass1_kernel() {
    int d2 = blockIdx.x * 256 + threadIdx.x;      // half2 column, 0..1023
    int c = blockIdx.y;
    int b = blockIdx.z;
    size_t base = ((size_t)b * L_ + (size_t)c * LCHUNK) * (D_ / 2) + d2;
    const __half2* gp = reinterpret_cast<const __half2*>(g_gate);
    const __half2* sp = reinterpret_cast<const __half2*>(g_bin);
    float2 a = make_float2(1.0f, 1.0f), h = make_float2(0.0f, 0.0f);
    #pragma unroll 4
    for (int t = 0; t < LCHUNK; t++) {
        float2 gt = __half22float2(gp[base + (size_t)t * (D_ / 2)]);
        float2 si = __half22float2(sp[base + (size_t)t * (D_ / 2)]);
        h.x = fmaf(gt.x, h.x, si.x * (1.0f - gt.x));
        h.y = fmaf(gt.y, h.y, si.y * (1.0f - gt.y));
        a.x *= gt.x; a.y *= gt.y;
    }
    size_t idx = ((size_t)b * NCHUNK + c) * (D_ / 2) + d2;
    reinterpret_cast<float2*>(g_cA)[idx] = a;
    reinterpret_cast<float2*>(g_cH)[idx] = h;
}

__global__ void scan_pass2_kernel() {
    int d2 = blockIdx.x * 256 + threadIdx.x;
    int b = blockIdx.y;
    float2 h = make_float2(0.0f, 0.0f);
    #pragma unroll
    for (int c = 0; c < NCHUNK; c++) {
        size_t idx = ((size_t)b * NCHUNK + c) * (D_ / 2) + d2;
        reinterpret_cast<float2*>(g_pre)[idx] = h;
        float2 a = reinterpret_cast<const float2*>(g_cA)[idx];
        float2 ch = reinterpret_cast<const float2*>(g_cH)[idx];
        h.x = fmaf(a.x, h.x, ch.x);
        h.y = fmaf(a.y, h.y, ch.y);
    }
}

// pass3: replay chunk from prefix, write swish(o) as fp16 (overwrites g_bin)
__global__ void scan_pass3_kernel() {
    int d2 = blockIdx.x * 256 + threadIdx.x;
    int c = blockIdx.y;
    int b = blockIdx.z;
    size_t base = ((size_t)b * L_ + (size_t)c * LCHUNK) * (D_ / 2) + d2;
    const __half2* gp = reinterpret_cast<const __half2*>(g_gate);
    __half2* sp = reinterpret_cast<__half2*>(g_bin);
    float2 h = reinterpret_cast<const float2*>(g_pre)[
        ((size_t)b * NCHUNK + c) * (D_ / 2) + d2];
    #pragma unroll 4
    for (int t = 0; t < LCHUNK; t++) {
        size_t p = base + (size_t)t * (D_ / 2);
        float2 gt = __half22float2(gp[p]);
        float2 si = __half22float2(sp[p]);
        h.x = fmaf(gt.x, h.x, si.x * (1.0f - gt.x));
        h.y = fmaf(gt.y, h.y, si.y * (1.0f - gt.y));
        float sw0 = h.x * fsigmoid(h.x);
        float sw1 = h.y * fsigmoid(h.y);
        sp[p] = __floats2half2_rn(sw0, sw1);     // swish(o) in place
    }
}

// ---------------------------------------------------------------------------
// RMSNorm(g)*weight*swish(o); writes fp16 for the output GEMM.
// ---------------------------------------------------------------------------
__global__ __launch_bounds__(256) void rms_gate_kernel(const float* __restrict__ gw) {
    const int m = blockIdx.x;
    const int tid = threadIdx.x;
    const uint2* grow = reinterpret_cast<const uint2*>(g_g  + (size_t)m * D_);
    const uint2* srow = reinterpret_cast<const uint2*>(g_bin + (size_t)m * D_);
    const float4* wrow = reinterpret_cast<const float4*>(gw);

    float gv[2][4];
    float ss = 0.0f;
    #pragma unroll
    for (int s = 0; s < 2; s++) {
        uint2 packed = grow[tid + s * 256];
        float2 p0 = __half22float2(*reinterpret_cast<__half2*>(&packed.x));
        float2 p1 = __half22float2(*reinterpret_cast<__half2*>(&packed.y));
        gv[s][0] = p0.x; gv[s][1] = p0.y; gv[s][2] = p1.x; gv[s][3] = p1.y;
        ss += p0.x * p0.x + p0.y * p0.y + p1.x * p1.x + p1.y * p1.y;
    }

    __shared__ float sh[8];
    __shared__ float tot;
    int lane = tid & 31, wid = tid >> 5;
    #pragma unroll
    for (int o = 16; o > 0; o >>= 1) ss += __shfl_xor_sync(0xffffffffu, ss, o);
    if (lane == 0) sh[wid] = ss;
    __syncthreads();
    if (wid == 0) {
        float v = (lane < 8) ? sh[lane] : 0.0f;
        #pragma unroll
        for (int o = 4; o > 0; o >>= 1) v += __shfl_xor_sync(0xffffffffu, v, o);
        if (lane == 0) tot = v;
    }
    __syncthreads();

    float rms = rsqrtf(tot * (1.0f / D_) + 1e-5f);

    #pragma unroll
    for (int s = 0; s < 2; s++) {
        uint2 spk = srow[tid + s * 256];
        float2 s0 = __half22float2(*reinterpret_cast<__half2*>(&spk.x));
        float2 s1 = __half22float2(*reinterpret_cast<__half2*>(&spk.y));
        float sw[4] = {s0.x, s0.y, s1.x, s1.y};
        float4 w4 = wrow[tid + s * 256];
        float wv[4] = {w4.x, w4.y, w4.z, w4.w};
        __half h[4];
        #pragma unroll
        for (int q = 0; q < 4; q++)
            h[q] = __float2half(gv[s][q] * rms * wv[q] * sw[q]);
        size_t b4 = (size_t)m * (D_ / 4) + tid + s * 256;
        reinterpret_cast<uint2*>(g_o)[b4] = *reinterpret_cast<uint2*>(h);
    }
}

// ---------------------------------------------------------------------------
extern "C" void kernel_launch(void* const* d_in, const int* in_sizes, int n_in,
                              void* d_out, int out_size)
{
    const float* X  = (const float*)d_in[0];
    const float* Wi = (const float*)d_in[1];
    const float* Wf = (const float*)d_in[2];
    const float* Wg = (const float*)d_in[3];
    const float* gw = (const float*)d_in[4];
    const float* Wo = (const float*)d_in[5];
    float* Y = (float*)d_out;

    static int inited = 0;
    static cudaStream_t s1;
    static cudaEvent_t evFork, evJoin;
    if (!inited) {
        cudaFuncSetAttribute(gemm_f16,
            cudaFuncAttributeMaxDynamicSharedMemorySize, SMEM_TOTAL);
        cudaStreamCreateWithFlags(&s1, cudaStreamNonBlocking);
        cudaEventCreateWithFlags(&evFork, cudaEventDisableTiming);
        cudaEventCreateWithFlags(&evJoin, cudaEventDisableTiming);
        inited = 1;
    }

    // fp32 -> fp16 converts
    convX_kernel<<<(M_ * D_ / 4) / 256, 256>>>(X);
    convW_kernel<<<dim3((D_ * D_ / 4) / 256, 4), 256>>>(Wi, Wf, Wg, Wo);

    // i + f projections (scan inputs)
    gemm_f16<<<dim3(D_ / 128, 2, M_ / 128), 256, SMEM_TOTAL>>>(1, Y);

    // fork: scan (DRAM-bound) runs on s1 concurrently with the g projection
    // (tensor-bound) on the main stream.
    cudaEventRecord(evFork, 0);
    cudaStreamWaitEvent(s1, evFork, 0);
    scan_pass1_kernel<<<dim3(D_ / 512, NCHUNK, B_), 256, 0, s1>>>();
    scan_pass2_kernel<<<dim3(D_ / 512, B_), 256, 0, s1>>>();
    scan_pass3_kernel<<<dim3(D_ / 512, NCHUNK, B_), 256, 0, s1>>>();
    cudaEventRecord(evJoin, s1);

    // g projection on the main stream (overlaps scan)
    gemm_f16<<<dim3(D_ / 128, 1, M_ / 128), 256, SMEM_TOTAL>>>(2, Y);

    // join, then rms + output GEMM
    cudaStreamWaitEvent(0, evJoin, 0);
    rms_gate_kernel<<<M_, 256>>>(gw);
    gemm_f16<<<dim3(D_ / 128, 1, M_ / 128), 256, SMEM_TOTAL>>>(0, Y);
}

// round 15
// speedup vs baseline: 1.5337x; 1.5337x over previous
#include <cuda_runtime.h>
#include <cuda_fp16.h>
#include <math.h>
#include <stdint.h>

#define B_ 4
#define L_ 4096
#define D_ 2048
#define M_ (B_*L_)            // 16384 rows
#define LCHUNK 64
#define NCHUNK (L_/LCHUNK)    // 64

// GEMM tiling: 128x128 tile, K chunk 64 fp16 (=128B row, SW128 swizzle)
#define KC 64
#define NKCH (D_/KC)          // 32
#define SUB 16384             // 128 rows * 128B
#define STAGE (2*SUB)         // A, B = 32KB
#define SMEM_TOTAL (2*STAGE)  // 64KB double buffered -> 2 CTAs/SM

// ---------------- scratch (device globals; no allocation allowed) ----------
__device__ __half g_gate[33554432];  // [M_, D_] sigmoid(f), fp16
__device__ __half g_bin [33554432];  // [M_, D_] silu(i); becomes swish(o) fp16
__device__ __half g_g   [33554432];  // [M_, D_] g projection, fp16
__device__ float g_cA  [B_*NCHUNK*D_];
__device__ float g_cH  [B_*NCHUNK*D_];
__device__ __half g_Xh[33554432];        // X (fp16 rounded)
__device__ __half g_Wh[4][4194304];      // Wi,Wf,Wg,Wo (fp16 rounded)
__device__ __half g_o[33554432];         // rms-gated out (fp16)

__device__ __forceinline__ float fsigmoid(float x) {
    return 1.0f / (1.0f + __expf(-x));
}

// ---------------------------- PTX helpers ----------------------------------
__device__ __forceinline__ uint32_t smem_u32(const void* p) {
    uint32_t a;
    asm("{ .reg .u64 t; cvta.to.shared.u64 t, %1; cvt.u32.u64 %0, t; }"
        : "=r"(a) : "l"(p));
    return a;
}
__device__ __forceinline__ uint32_t swz128(uint32_t off) {
    return off ^ ((off >> 3) & 0x70);
}
__device__ __forceinline__ void cpa16(uint32_t s, const void* g) {
    asm volatile("cp.async.cg.shared.global [%0], [%1], 16;" :: "r"(s), "l"(g));
}
#define CPA_COMMIT()  asm volatile("cp.async.commit_group;" ::: "memory")
#define CPA_WAIT1()   asm volatile("cp.async.wait_group 1;" ::: "memory")
#define CPA_WAIT0()   asm volatile("cp.async.wait_group 0;" ::: "memory")

__device__ __forceinline__ void ldsm4(uint32_t* r, uint32_t addr) {
    asm volatile("ldmatrix.sync.aligned.m8n8.x4.shared.b16 {%0,%1,%2,%3}, [%4];"
        : "=r"(r[0]), "=r"(r[1]), "=r"(r[2]), "=r"(r[3]) : "r"(addr));
}
__device__ __forceinline__ void mma_f16(float* c, const uint32_t* a,
                                        uint32_t b0, uint32_t b1) {
    asm volatile(
        "mma.sync.aligned.m16n8k16.row.col.f32.f16.f16.f32 "
        "{%0,%1,%2,%3}, {%4,%5,%6,%7}, {%8,%9}, {%0,%1,%2,%3};"
        : "+f"(c[0]), "+f"(c[1]), "+f"(c[2]), "+f"(c[3])
        : "r"(a[0]), "r"(a[1]), "r"(a[2]), "r"(a[3]), "r"(b0), "r"(b1));
}

// ---------------------------------------------------------------------------
// fp32 -> fp16 converts
// ---------------------------------------------------------------------------
__global__ __launch_bounds__(256) void convX_kernel(const float* __restrict__ src) {
    int i = blockIdx.x * 256 + threadIdx.x;          // float4 index
    float4 v = reinterpret_cast<const float4*>(src)[i];
    __half h[4] = {__float2half(v.x), __float2half(v.y),
                   __float2half(v.z), __float2half(v.w)};
    reinterpret_cast<uint2*>(g_Xh)[i] = *reinterpret_cast<uint2*>(h);
}

__global__ __launch_bounds__(256) void convW_kernel(
    const float* __restrict__ w0, const float* __restrict__ w1,
    const float* __restrict__ w2, const float* __restrict__ w3) {
    const float* src = (blockIdx.y == 0) ? w0 : (blockIdx.y == 1) ? w1
                     : (blockIdx.y == 2) ? w2 : w3;
    int i = blockIdx.x * 256 + threadIdx.x;          // float4 index
    float4 v = reinterpret_cast<const float4*>(src)[i];
    __half h[4] = {__float2half(v.x), __float2half(v.y),
                   __float2half(v.z), __float2half(v.w)};
    reinterpret_cast<uint2*>(g_Wh[blockIdx.y])[i] = *reinterpret_cast<uint2*>(h);
}

// ---------------------------------------------------------------------------
// fp16 HMMA GEMM: C[m,n] = sum_k A[m,k]*B[n,k], 1 MMA per product.
// Tile 128x128, K chunk 64, 2-stage double buffer, 2 CTAs/SM. (R11 config)
// sel=1: A=X, blockIdx.y: 0 -> Wi(silu)->g_bin, 1 -> Wf(sigm)->g_gate,
//        2 -> Wg(raw)->g_g.     sel=0: A=g_o, Wo (raw) -> Cext (fp32)
// ---------------------------------------------------------------------------
__global__ __launch_bounds__(256, 2) void gemm_f16(int sel, float* Cext) {
    extern __shared__ char smem[];
    const uint32_t sb = smem_u32(smem);
    const int tid  = threadIdx.x;
    const int lane = tid & 31;
    const int wid  = tid >> 5;
    const int wm   = wid & 3;      // 4 warps over M (32 rows each)
    const int wn   = wid >> 2;     // 2 warps over N (64 cols each)
    const int bn = blockIdx.x;
    const int bm = blockIdx.z;

    const __half *Aw, *Bw;
    __half* Ch = nullptr;
    int mode;                           // 0 silu, 1 sigmoid, 2 raw-f16, 3 raw-f32
    if (sel == 1) {
        Aw = g_Xh;
        if (blockIdx.y == 0)      { Bw = g_Wh[0]; Ch = g_bin;  mode = 0; }
        else if (blockIdx.y == 1) { Bw = g_Wh[1]; Ch = g_gate; mode = 1; }
        else                      { Bw = g_Wh[2]; Ch = g_g;    mode = 2; }
    } else { Aw = g_o; Bw = g_Wh[3]; mode = 3; }

    const size_t rowA = (size_t)bm * 128;
    const size_t rowB = (size_t)bn * 128;

    float acc[2][8][4];
    #pragma unroll
    for (int ma = 0; ma < 2; ma++)
        #pragma unroll
        for (int g = 0; g < 8; g++)
            #pragma unroll
            for (int q = 0; q < 4; q++) acc[ma][g][q] = 0.0f;

    // strength-reduced prefetch
    const int prow = tid >> 3;            // 0..31
    const int pch  = tid & 7;             // 16B chunk in 128B row
    const uint32_t so0 = swz128((uint32_t)prow * 128 + pch * 16);
    const __half* pA = Aw + (rowA + prow) * D_ + pch * 8;
    const __half* pB = Bw + (rowB + prow) * D_ + pch * 8;

    auto prefetch = [&](int c) {
        const uint32_t st = sb + (uint32_t)(c & 1) * STAGE;
        #pragma unroll
        for (int r = 0; r < 4; r++) {
            uint32_t so = so0 + r * 4096;
            size_t   go = (size_t)r * 32 * D_;
            cpa16(st + so,       pA + go);
            cpa16(st + SUB + so, pB + go);
        }
        pA += KC; pB += KC;
        CPA_COMMIT();
    };

    prefetch(0);
    prefetch(1);

    // ldsm bases, pre-swizzled (bits 5,6 of base are 0 pre-swizzle, so
    // swz128(base + ks*32) == swz128(base) ^ (ks*32)).
    const int rowL = lane & 15;
    const int colL = lane >> 4;
    uint32_t arbS[2], brbS[4];
    #pragma unroll
    for (int ma = 0; ma < 2; ma++)
        arbS[ma] = swz128((uint32_t)(wm * 32 + ma * 16 + rowL) * 128 + colL * 16);
    #pragma unroll
    for (int g16 = 0; g16 < 4; g16++)
        brbS[g16] = swz128((uint32_t)(wn * 64 + g16 * 16 + rowL) * 128 + colL * 16)
                  + SUB;

    for (int c = 0; c < NKCH; c++) {
        if (c < NKCH - 1) { CPA_WAIT1(); } else { CPA_WAIT0(); }
        __syncthreads();

        const uint32_t st = sb + (uint32_t)(c & 1) * STAGE;
        #pragma unroll
        for (int ks = 0; ks < 4; ks++) {
            const uint32_t kx = (uint32_t)ks * 32;
            uint32_t ah[2][4];
            #pragma unroll
            for (int ma = 0; ma < 2; ma++)
                ldsm4(ah[ma], st + (arbS[ma] ^ kx));
            #pragma unroll
            for (int g16 = 0; g16 < 4; g16++) {
                uint32_t bh[4];
                ldsm4(bh, st + (brbS[g16] ^ kx));
                #pragma unroll
                for (int na = 0; na < 2; na++)
                    #pragma unroll
                    for (int ma = 0; ma < 2; ma++)
                        mma_f16(acc[ma][g16 * 2 + na], ah[ma], bh[na], bh[na + 2]);
            }
        }
        __syncthreads();
        if (c + 2 < NKCH) prefetch(c + 2);
    }

    // epilogue: fused activation; f16 stores for intermediates, f32 for out
    #pragma unroll
    for (int ma = 0; ma < 2; ma++) {
        #pragma unroll
        for (int g = 0; g < 8; g++) {
            int n = (int)rowB + wn * 64 + (g >> 1) * 16 + (g & 1) * 8 + (lane & 3) * 2;
            size_t m0 = rowA + wm * 32 + ma * 16 + (lane >> 2);
            #pragma unroll
            for (int h = 0; h < 2; h++) {           // h=0: rows, h=1: rows+8
                float v0 = acc[ma][g][h * 2 + 0];
                float v1 = acc[ma][g][h * 2 + 1];
                if (mode == 0)      { v0 = v0 * fsigmoid(v0); v1 = v1 * fsigmoid(v1); }
                else if (mode == 1) { v0 = fsigmoid(v0);      v1 = fsigmoid(v1); }
                size_t off = (m0 + h * 8) * D_ + n;
                if (mode == 3) {
                    *reinterpret_cast<float2*>(&Cext[off]) = make_float2(v0, v1);
                } else {
                    *reinterpret_cast<__half2*>(&Ch[off]) =
                        __floats2half2_rn(v0, v1);
                }
            }
        }
    }
}

// ---------------------------------------------------------------------------
// Chunked linear-recurrence scan: h_t = a_t*h_{t-1} + b_t,  b_t = si*(1-a_t)
// fp16 storage, fp32 math; 2 channels (half2) per thread.
// LCHUNK=64 (1024 blocks -> better DRAM utilization); pass2 folded into pass3.
// ---------------------------------------------------------------------------
__global__ void scan_pass1_kernel() {
    int d2 = blockIdx.x * 256 + threadIdx.x;      // half2 column, 0..1023
    int c = blockIdx.y;
    int b = blockIdx.z;
    size_t base = ((size_t)b * L_ + (size_t)c * LCHUNK) * (D_ / 2) + d2;
    const __half2* gp = reinterpret_cast<const __half2*>(g_gate);
    const __half2* sp = reinterpret_cast<const __half2*>(g_bin);
    float2 a = make_float2(1.0f, 1.0f), h = make_float2(0.0f, 0.0f);
    #pragma unroll 4
    for (int t = 0; t < LCHUNK; t++) {
        float2 gt = __half22float2(gp[base + (size_t)t * (D_ / 2)]);
        float2 si = __half22float2(sp[base + (size_t)t * (D_ / 2)]);
        h.x = fmaf(gt.x, h.x, si.x * (1.0f - gt.x));
        h.y = fmaf(gt.y, h.y, si.y * (1.0f - gt.y));
        a.x *= gt.x; a.y *= gt.y;
    }
    size_t idx = ((size_t)b * NCHUNK + c) * (D_ / 2) + d2;
    reinterpret_cast<float2*>(g_cA)[idx] = a;
    reinterpret_cast<float2*>(g_cH)[idx] = h;
}

// pass3: fold chunk-prefix from cA/cH (L2-resident, <=63 steps), then replay
// chunk and write swish(o) fp16 in place of silu(i).
__global__ void scan_pass3_kernel() {
    int d2 = blockIdx.x * 256 + threadIdx.x;
    int c = blockIdx.y;
    int b = blockIdx.z;
    // prefix: h_pre = fold_{j<c} (cA[j], cH[j])
    float2 h = make_float2(0.0f, 0.0f);
    size_t cbase = (size_t)b * NCHUNK * (D_ / 2) + d2;
    for (int j = 0; j < c; j++) {
        size_t idx = cbase + (size_t)j * (D_ / 2);
        float2 a  = reinterpret_cast<const float2*>(g_cA)[idx];
        float2 ch = reinterpret_cast<const float2*>(g_cH)[idx];
        h.x = fmaf(a.x, h.x, ch.x);
        h.y = fmaf(a.y, h.y, ch.y);
    }
    // replay chunk
    size_t base = ((size_t)b * L_ + (size_t)c * LCHUNK) * (D_ / 2) + d2;
    const __half2* gp = reinterpret_cast<const __half2*>(g_gate);
    __half2* sp = reinterpret_cast<__half2*>(g_bin);
    #pragma unroll 4
    for (int t = 0; t < LCHUNK; t++) {
        size_t p = base + (size_t)t * (D_ / 2);
        float2 gt = __half22float2(gp[p]);
        float2 si = __half22float2(sp[p]);
        h.x = fmaf(gt.x, h.x, si.x * (1.0f - gt.x));
        h.y = fmaf(gt.y, h.y, si.y * (1.0f - gt.y));
        float sw0 = h.x * fsigmoid(h.x);
        float sw1 = h.y * fsigmoid(h.y);
        sp[p] = __floats2half2_rn(sw0, sw1);     // swish(o) in place
    }
}

// ---------------------------------------------------------------------------
// RMSNorm(g)*weight*swish(o); writes fp16 for the output GEMM.
// ---------------------------------------------------------------------------
__global__ __launch_bounds__(256) void rms_gate_kernel(const float* __restrict__ gw) {
    const int m = blockIdx.x;
    const int tid = threadIdx.x;
    const uint2* grow = reinterpret_cast<const uint2*>(g_g  + (size_t)m * D_);
    const uint2* srow = reinterpret_cast<const uint2*>(g_bin + (size_t)m * D_);
    const float4* wrow = reinterpret_cast<const float4*>(gw);

    float gv[2][4];
    float ss = 0.0f;
    #pragma unroll
    for (int s = 0; s < 2; s++) {
        uint2 packed = grow[tid + s * 256];
        float2 p0 = __half22float2(*reinterpret_cast<__half2*>(&packed.x));
        float2 p1 = __half22float2(*reinterpret_cast<__half2*>(&packed.y));
        gv[s][0] = p0.x; gv[s][1] = p0.y; gv[s][2] = p1.x; gv[s][3] = p1.y;
        ss += p0.x * p0.x + p0.y * p0.y + p1.x * p1.x + p1.y * p1.y;
    }

    __shared__ float sh[8];
    __shared__ float tot;
    int lane = tid & 31, wid = tid >> 5;
    #pragma unroll
    for (int o = 16; o > 0; o >>= 1) ss += __shfl_xor_sync(0xffffffffu, ss, o);
    if (lane == 0) sh[wid] = ss;
    __syncthreads();
    if (wid == 0) {
        float v = (lane < 8) ? sh[lane] : 0.0f;
        #pragma unroll
        for (int o = 4; o > 0; o >>= 1) v += __shfl_xor_sync(0xffffffffu, v, o);
        if (lane == 0) tot = v;
    }
    __syncthreads();

    float rms = rsqrtf(tot * (1.0f / D_) + 1e-5f);

    #pragma unroll
    for (int s = 0; s < 2; s++) {
        uint2 spk = srow[tid + s * 256];
        float2 s0 = __half22float2(*reinterpret_cast<__half2*>(&spk.x));
        float2 s1 = __half22float2(*reinterpret_cast<__half2*>(&spk.y));
        float sw[4] = {s0.x, s0.y, s1.x, s1.y};
        float4 w4 = wrow[tid + s * 256];
        float wv[4] = {w4.x, w4.y, w4.z, w4.w};
        __half h[4];
        #pragma unroll
        for (int q = 0; q < 4; q++)
            h[q] = __float2half(gv[s][q] * rms * wv[q] * sw[q]);
        size_t b4 = (size_t)m * (D_ / 4) + tid + s * 256;
        reinterpret_cast<uint2*>(g_o)[b4] = *reinterpret_cast<uint2*>(h);
    }
}

// ---------------------------------------------------------------------------
extern "C" void kernel_launch(void* const* d_in, const int* in_sizes, int n_in,
                              void* d_out, int out_size)
{
    const float* X  = (const float*)d_in[0];
    const float* Wi = (const float*)d_in[1];
    const float* Wf = (const float*)d_in[2];
    const float* Wg = (const float*)d_in[3];
    const float* gw = (const float*)d_in[4];
    const float* Wo = (const float*)d_in[5];
    float* Y = (float*)d_out;

    static int smem_set = 0;
    if (!smem_set) {
        cudaFuncSetAttribute(gemm_f16,
            cudaFuncAttributeMaxDynamicSharedMemorySize, SMEM_TOTAL);
        smem_set = 1;
    }

    // fp32 -> fp16 converts
    convX_kernel<<<(M_ * D_ / 4) / 256, 256>>>(X);
    convW_kernel<<<dim3((D_ * D_ / 4) / 256, 4), 256>>>(Wi, Wf, Wg, Wo);

    // i/f/g projections (1-MMA each): grid y = weight (single launch)
    gemm_f16<<<dim3(D_ / 128, 3, M_ / 128), 256, SMEM_TOTAL>>>(1, Y);

    // scan: pass1 (per-chunk reduce), pass3 (prefix-fold + replay)
    scan_pass1_kernel<<<dim3(D_ / 512, NCHUNK, B_), 256>>>();
    scan_pass3_kernel<<<dim3(D_ / 512, NCHUNK, B_), 256>>>();

    rms_gate_kernel<<<M_, 256>>>(gw);

    // out @ Wo^T -> Y (1-MMA)
    gemm_f16<<<dim3(D_ / 128, 1, M_ / 128), 256, SMEM_TOTAL>>>(0, Y);
}